// round 2
// baseline (speedup 1.0000x reference)
#include <cuda_runtime.h>
#include <cuda_bf16.h>
#include <cstdint>

#define D 128
#define MAXNZ 2048
#define BM 16
#define MAXB 4096

// scratch for the aggregated (B, D) intermediate — allocation-free per rules
__device__ float g_agg[(size_t)MAXB * D];

// ---------------------------------------------------------------------------
// Kernel 1: per-batch-row sparse aggregation.
//   agg[b][d] = sum_n F[uid_b][n] * E[n][d]   (skip the ~99.7% zeros of F)
// One CTA per batch element, 128 threads.
//   Phase 1: scan F row (float4), compact nonzeros (idx, w) to smem.
//   Phase 2: thread d owns output dim d, accumulates over the nonzero list.
// ---------------------------------------------------------------------------
__global__ __launch_bounds__(128) void agg_kernel(
    const int* __restrict__ ids,
    const float* __restrict__ F,
    const float* __restrict__ E,
    int n_total,
    float* __restrict__ agg)
{
    __shared__ int   s_idx[MAXNZ];
    __shared__ float s_w[MAXNZ];
    __shared__ int   s_cnt;

    const int tid = threadIdx.x;
    if (tid == 0) s_cnt = 0;
    __syncthreads();

    const int uid = ids[blockIdx.x];
    const float* __restrict__ row = F + (size_t)uid * (size_t)n_total;

    if (((n_total & 3) == 0) && ((((uintptr_t)row) & 15) == 0)) {
        // vectorized scan: 16 B per thread per iteration
        const float4* __restrict__ row4 = (const float4*)row;
        const int nvec = n_total >> 2;
        for (int i = tid; i < nvec; i += 128) {
            float4 v = row4[i];
            if (v.x != 0.0f) { int p = atomicAdd(&s_cnt, 1); if (p < MAXNZ) { s_idx[p] = 4*i + 0; s_w[p] = v.x; } }
            if (v.y != 0.0f) { int p = atomicAdd(&s_cnt, 1); if (p < MAXNZ) { s_idx[p] = 4*i + 1; s_w[p] = v.y; } }
            if (v.z != 0.0f) { int p = atomicAdd(&s_cnt, 1); if (p < MAXNZ) { s_idx[p] = 4*i + 2; s_w[p] = v.z; } }
            if (v.w != 0.0f) { int p = atomicAdd(&s_cnt, 1); if (p < MAXNZ) { s_idx[p] = 4*i + 3; s_w[p] = v.w; } }
        }
    } else {
        for (int i = tid; i < n_total; i += 128) {
            float v = row[i];
            if (v != 0.0f) { int p = atomicAdd(&s_cnt, 1); if (p < MAXNZ) { s_idx[p] = i; s_w[p] = v; } }
        }
    }
    __syncthreads();

    const int cnt = min(s_cnt, MAXNZ);
    const int d = tid;  // thread d -> output dim d
    float acc = 0.0f;

    int j = 0;
    // unroll-4 for memory-level parallelism on the E row loads (E is L2-resident)
    for (; j + 4 <= cnt; j += 4) {
        const float w0 = s_w[j + 0], w1 = s_w[j + 1], w2 = s_w[j + 2], w3 = s_w[j + 3];
        const float e0 = E[(size_t)s_idx[j + 0] * D + d];
        const float e1 = E[(size_t)s_idx[j + 1] * D + d];
        const float e2 = E[(size_t)s_idx[j + 2] * D + d];
        const float e3 = E[(size_t)s_idx[j + 3] * D + d];
        acc += w0 * e0;
        acc += w1 * e1;
        acc += w2 * e2;
        acc += w3 * e3;
    }
    for (; j < cnt; ++j)
        acc += s_w[j] * E[(size_t)s_idx[j] * D + d];

    agg[(size_t)blockIdx.x * D + d] = acc;
}

// ---------------------------------------------------------------------------
// Kernel 2: out[b][d] = bias[d] + sum_k agg[b][k] * W[d][k]
// Register-tiled 16x128 per CTA, 128 threads (32 x-lanes, 4 y-lanes),
// each thread computes a 4(row) x 4(col, stride-32) tile.
// W is transposed into padded smem (stride 129 -> conflict-free ld/st).
// ---------------------------------------------------------------------------
__global__ __launch_bounds__(128) void lin_kernel(
    const float* __restrict__ agg,
    const float* __restrict__ W,
    const float* __restrict__ bias,
    float* __restrict__ out,
    int B)
{
    extern __shared__ float sWt[];        // [128][129] : sWt[k*129 + d] = W[d][k]
    __shared__ float sA[BM * D];          // 16 x 128 agg tile

    const int tid = threadIdx.x;
    const int tx  = tid & 31;             // 0..31 -> d lanes
    const int ty  = tid >> 5;             // 0..3  -> row groups

    // load + transpose W: gmem read coalesced, smem write bank-conflict-free
    for (int i = tid; i < D * D; i += 128) {
        const int d = i >> 7;
        const int k = i & 127;
        sWt[k * 129 + d] = W[i];
    }

    // load agg tile
    const int row0 = blockIdx.x * BM;
    for (int i = tid; i < BM * D; i += 128) {
        const int r  = i >> 7;
        const int k  = i & 127;
        const int rr = row0 + r;
        sA[i] = (rr < B) ? agg[(size_t)rr * D + k] : 0.0f;
    }
    __syncthreads();

    float acc[4][4];
    float bv[4];
#pragma unroll
    for (int j = 0; j < 4; ++j) {
        bv[j] = bias[tx + 32 * j];
#pragma unroll
        for (int i = 0; i < 4; ++i) acc[i][j] = 0.0f;
    }

#pragma unroll 8
    for (int k = 0; k < D; ++k) {
        float a[4], w[4];
#pragma unroll
        for (int i = 0; i < 4; ++i) a[i] = sA[(ty * 4 + i) * D + k];      // warp broadcast
#pragma unroll
        for (int j = 0; j < 4; ++j) w[j] = sWt[k * 129 + tx + 32 * j];    // conflict-free
#pragma unroll
        for (int i = 0; i < 4; ++i)
#pragma unroll
            for (int j = 0; j < 4; ++j)
                acc[i][j] += a[i] * w[j];
    }

#pragma unroll
    for (int i = 0; i < 4; ++i) {
        const int r = row0 + ty * 4 + i;
        if (r < B) {
#pragma unroll
            for (int j = 0; j < 4; ++j)
                out[(size_t)r * D + tx + 32 * j] = acc[i][j] + bv[j];
        }
    }
}

extern "C" void kernel_launch(void* const* d_in, const int* in_sizes, int n_in,
                              void* d_out, int out_size)
{
    const int*   ids  = (const int*)  d_in[0];
    const float* F    = (const float*)d_in[1];
    const float* E    = (const float*)d_in[2];
    const float* W    = (const float*)d_in[3];
    const float* bias = (const float*)d_in[4];
    float* out = (float*)d_out;

    const int B       = in_sizes[0];
    const int n_total = in_sizes[2] / D;

    float* agg;
    cudaGetSymbolAddress((void**)&agg, g_agg);

    agg_kernel<<<B, 128>>>(ids, F, E, n_total, agg);

    const int smem2 = 129 * 128 * (int)sizeof(float);  // 66048 B > 48 KB default
    cudaFuncSetAttribute(lin_kernel, cudaFuncAttributeMaxDynamicSharedMemorySize, smem2);
    lin_kernel<<<(B + BM - 1) / BM, 128, smem2>>>(agg, W, bias, out, B);
}

// round 3
// speedup vs baseline: 1.8183x; 1.8183x over previous
#include <cuda_runtime.h>
#include <cuda_bf16.h>
#include <cstdint>

#define D 128
#define MAXNZ 512
#define BM 16
#define MAXB 4096

// scratch for the aggregated (B, D) intermediate — allocation-free per rules
__device__ float g_agg[(size_t)MAXB * D];

// ---------------------------------------------------------------------------
// Kernel 1: per-batch-row sparse aggregation.
//   agg[b][d] = sum_n F[uid_b][n] * E[n][d]   (skip the ~99.7% zeros of F)
// One CTA per batch element, 128 threads.
// ---------------------------------------------------------------------------
__global__ __launch_bounds__(128) void agg_kernel(
    const int* __restrict__ ids,
    const float* __restrict__ F,
    const float* __restrict__ E,
    int n_total,
    float* __restrict__ agg)
{
    __shared__ int   s_idx[MAXNZ];
    __shared__ float s_w[MAXNZ];
    __shared__ int   s_cnt;

    const int tid = threadIdx.x;
    if (tid == 0) s_cnt = 0;
    __syncthreads();

    const int uid = ids[blockIdx.x];
    const float* __restrict__ row = F + (size_t)uid * (size_t)n_total;

    if (((n_total & 3) == 0) && ((((uintptr_t)row) & 15) == 0)) {
        const float4* __restrict__ row4 = (const float4*)row;
        const int nvec = n_total >> 2;
        for (int i = tid; i < nvec; i += 128) {
            float4 v = row4[i];
            if (v.x != 0.0f) { int p = atomicAdd(&s_cnt, 1); if (p < MAXNZ) { s_idx[p] = 4*i + 0; s_w[p] = v.x; } }
            if (v.y != 0.0f) { int p = atomicAdd(&s_cnt, 1); if (p < MAXNZ) { s_idx[p] = 4*i + 1; s_w[p] = v.y; } }
            if (v.z != 0.0f) { int p = atomicAdd(&s_cnt, 1); if (p < MAXNZ) { s_idx[p] = 4*i + 2; s_w[p] = v.z; } }
            if (v.w != 0.0f) { int p = atomicAdd(&s_cnt, 1); if (p < MAXNZ) { s_idx[p] = 4*i + 3; s_w[p] = v.w; } }
        }
    } else {
        for (int i = tid; i < n_total; i += 128) {
            float v = row[i];
            if (v != 0.0f) { int p = atomicAdd(&s_cnt, 1); if (p < MAXNZ) { s_idx[p] = i; s_w[p] = v; } }
        }
    }
    __syncthreads();

    const int cnt = min(s_cnt, MAXNZ);
    const int d = tid;
    float acc = 0.0f;

    int j = 0;
    for (; j + 4 <= cnt; j += 4) {
        const float w0 = s_w[j + 0], w1 = s_w[j + 1], w2 = s_w[j + 2], w3 = s_w[j + 3];
        const float e0 = E[(size_t)s_idx[j + 0] * D + d];
        const float e1 = E[(size_t)s_idx[j + 1] * D + d];
        const float e2 = E[(size_t)s_idx[j + 2] * D + d];
        const float e3 = E[(size_t)s_idx[j + 3] * D + d];
        acc += w0 * e0;
        acc += w1 * e1;
        acc += w2 * e2;
        acc += w3 * e3;
    }
    for (; j < cnt; ++j)
        acc += s_w[j] * E[(size_t)s_idx[j] * D + d];

    agg[(size_t)blockIdx.x * D + d] = acc;
}

// ---------------------------------------------------------------------------
// Kernel 2: out[b][d] = bias[d] + sum_k agg[b][k] * W[d][k]
// 256 threads (8 warps), BM=16 rows per CTA, grid = B/16.
// W staged into smem ROW-MAJOR with stride 129: bank of sW[d*129+k] is
// (d+k)%32, so lanes d=tx+32j at fixed k are conflict-free — no transpose
// needed. Each thread computes a 2(row) x 4(col) register tile.
// ---------------------------------------------------------------------------
__global__ __launch_bounds__(256) void lin_kernel(
    const float* __restrict__ agg,
    const float* __restrict__ W,
    const float* __restrict__ bias,
    float* __restrict__ out,
    int B)
{
    extern __shared__ float smem[];
    float* sW = smem;                 // [128][129]  sW[d*129+k] = W[d][k]
    float* sA = smem + 128 * 129;     // [16][128]

    const int tid = threadIdx.x;
    const int tx  = tid & 31;         // d lanes
    const int ty  = tid >> 5;         // 0..7 -> row pairs

    // stage W: straight float4 copy, 16 LDG.128 per thread (high MLP)
    {
        const float4* __restrict__ W4 = (const float4*)W;
#pragma unroll
        for (int t = 0; t < 16; ++t) {
            const int i4 = tid + t * 256;        // 0..4095
            const int dd = i4 >> 5;              // row
            const int k4 = (i4 & 31) << 2;       // col group
            float4 v = W4[i4];
            float* dst = &sW[dd * 129 + k4];
            dst[0] = v.x; dst[1] = v.y; dst[2] = v.z; dst[3] = v.w;
        }
    }

    // stage agg tile: 2 float4 per thread
    const int row0 = blockIdx.x * BM;
    {
        const float4* __restrict__ A4 = (const float4*)(agg + (size_t)row0 * D);
        float4* __restrict__ sA4 = (float4*)sA;
#pragma unroll
        for (int t = 0; t < 2; ++t) {
            const int i4 = tid + t * 256;        // 0..511 (16*128/4)
            sA4[i4] = A4[i4];
        }
    }
    __syncthreads();

    float acc[2][4];
    float bv[4];
#pragma unroll
    for (int j = 0; j < 4; ++j) {
        bv[j] = bias[tx + 32 * j];
#pragma unroll
        for (int i = 0; i < 2; ++i) acc[i][j] = 0.0f;
    }

#pragma unroll 8
    for (int k = 0; k < D; ++k) {
        float a0 = sA[(ty * 2 + 0) * D + k];     // warp broadcast
        float a1 = sA[(ty * 2 + 1) * D + k];
        float w[4];
#pragma unroll
        for (int j = 0; j < 4; ++j)
            w[j] = sW[(tx + 32 * j) * 129 + k];  // conflict-free: bank (d+k)%32
#pragma unroll
        for (int j = 0; j < 4; ++j) {
            acc[0][j] += a0 * w[j];
            acc[1][j] += a1 * w[j];
        }
    }

#pragma unroll
    for (int i = 0; i < 2; ++i) {
        const int r = row0 + ty * 2 + i;
        if (r < B) {
#pragma unroll
            for (int j = 0; j < 4; ++j)
                out[(size_t)r * D + tx + 32 * j] = acc[i][j] + bv[j];
        }
    }
}

extern "C" void kernel_launch(void* const* d_in, const int* in_sizes, int n_in,
                              void* d_out, int out_size)
{
    const int*   ids  = (const int*)  d_in[0];
    const float* F    = (const float*)d_in[1];
    const float* E    = (const float*)d_in[2];
    const float* W    = (const float*)d_in[3];
    const float* bias = (const float*)d_in[4];
    float* out = (float*)d_out;

    const int B       = in_sizes[0];
    const int n_total = in_sizes[2] / D;

    float* agg;
    cudaGetSymbolAddress((void**)&agg, g_agg);

    agg_kernel<<<B, 128>>>(ids, F, E, n_total, agg);

    const int smem2 = (128 * 129 + BM * D) * (int)sizeof(float);  // ~74 KB
    cudaFuncSetAttribute(lin_kernel, cudaFuncAttributeMaxDynamicSharedMemorySize, smem2);
    lin_kernel<<<(B + BM - 1) / BM, 256, smem2>>>(agg, W, bias, out, B);
}